// round 16
// baseline (speedup 1.0000x reference)
#include <cuda_runtime.h>
#include <cuda_fp16.h>
#include <math.h>
#include <stdint.h>

#define D_EMBED 2048
#define NHEAD   8
#define HDIM    256
#define BATCH   32
#define SEQ     256
#define ROWS    (BATCH*SEQ)   /* 8192 */
#define DFF     (4*D_EMBED)   /* 8192 */
#define BH      (BATCH*NHEAD) /* 256 */
#define NQKV    (3*D_EMBED)   /* 6144 */

// ---------------- scratch (device globals; no runtime allocation) -------------
__device__ __half g_h  [ROWS*D_EMBED];
__device__ __half g_qkv[(size_t)ROWS*NQKV];
__device__ __half g_vt [ROWS*D_EMBED];
__device__ __half g_sh [BH*SEQ*SEQ];
__device__ __half g_ao [ROWS*D_EMBED];
__device__ float  g_x1 [ROWS*D_EMBED];
__device__ __half g_h2 [ROWS*D_EMBED];
__device__ __half g_m1 [(size_t)ROWS*DFF];
__device__ float  g_part[(size_t)2*ROWS*D_EMBED];   /* split-K partials */
__device__ __half g_wqkvt[(size_t)NQKV*D_EMBED];
__device__ __half g_wot[D_EMBED*D_EMBED];
__device__ __half g_w1t[(size_t)D_EMBED*DFF];
__device__ __half g_w2t[(size_t)D_EMBED*DFF];
__device__ float  g_bqkv[NQKV];

// ---------------- helpers ------------------------------------------------------
__device__ __forceinline__ uint32_t smem_u32(const void* p) {
    uint32_t a;
    asm("{ .reg .u64 t; cvta.to.shared.u64 t, %1; cvt.u32.u64 %0, t; }" : "=r"(a) : "l"(p));
    return a;
}
__device__ __forceinline__ void cp16(uint32_t sdst, const void* gsrc) {
    asm volatile("cp.async.cg.shared.global [%0], [%1], 16;" :: "r"(sdst), "l"(gsrc));
}
#define CP_COMMIT() asm volatile("cp.async.commit_group;" ::: "memory")
template<int N>
__device__ __forceinline__ void cp_wait() {
    asm volatile("cp.async.wait_group %0;" :: "n"(N) : "memory");
}

__device__ __forceinline__ void mma16(float* c, const uint32_t a[4],
                                      uint32_t b0, uint32_t b1) {
    asm volatile(
        "mma.sync.aligned.m16n8k16.row.col.f32.f16.f16.f32 "
        "{%0,%1,%2,%3}, {%4,%5,%6,%7}, {%8,%9}, {%0,%1,%2,%3};"
        : "+f"(c[0]), "+f"(c[1]), "+f"(c[2]), "+f"(c[3])
        : "r"(a[0]), "r"(a[1]), "r"(a[2]), "r"(a[3]), "r"(b0), "r"(b1));
}
__device__ __forceinline__ void ldsm4(uint32_t& r0, uint32_t& r1, uint32_t& r2,
                                      uint32_t& r3, uint32_t addr) {
    asm volatile("ldmatrix.sync.aligned.m8n8.x4.shared.b16 {%0,%1,%2,%3}, [%4];"
                 : "=r"(r0), "=r"(r1), "=r"(r2), "=r"(r3) : "r"(addr));
}

// ---------------- layernorm (fp32 in -> fp16 out), warp-shuffle reductions -----
__global__ void __launch_bounds__(256) ln_kernel(const float* __restrict__ x,
                                                 const float* __restrict__ g,
                                                 const float* __restrict__ b,
                                                 __half* __restrict__ oh)
{
    __shared__ float wsum[8], wsq[8];
    const int row = blockIdx.x;
    const int tid = threadIdx.x;
    const int lane = tid & 31, wid = tid >> 5;
    const float* xr = x + (size_t)row * D_EMBED + tid * 8;

    const float4 a = *(const float4*)(xr);
    const float4 c = *(const float4*)(xr + 4);
    float v[8] = {a.x, a.y, a.z, a.w, c.x, c.y, c.z, c.w};

    float s = 0.f;
#pragma unroll
    for (int i = 0; i < 8; i++) s += v[i];
#pragma unroll
    for (int o = 16; o > 0; o >>= 1) s += __shfl_xor_sync(0xFFFFFFFFu, s, o);
    if (lane == 0) wsum[wid] = s;
    __syncthreads();
    float tot = 0.f;
#pragma unroll
    for (int i = 0; i < 8; i++) tot += wsum[i];
    const float mean = tot * (1.0f / D_EMBED);

    float q = 0.f;
#pragma unroll
    for (int i = 0; i < 8; i++) { const float d = v[i] - mean; q += d * d; }
#pragma unroll
    for (int o = 16; o > 0; o >>= 1) q += __shfl_xor_sync(0xFFFFFFFFu, q, o);
    if (lane == 0) wsq[wid] = q;
    __syncthreads();
    float totq = 0.f;
#pragma unroll
    for (int i = 0; i < 8; i++) totq += wsq[i];
    const float rstd = rsqrtf(totq * (1.0f / D_EMBED) + 1e-5f);

    const float4 g0 = *(const float4*)(g + tid * 8);
    const float4 g1 = *(const float4*)(g + tid * 8 + 4);
    const float4 b0 = *(const float4*)(b + tid * 8);
    const float4 b1 = *(const float4*)(b + tid * 8 + 4);
    const float gg[8] = {g0.x, g0.y, g0.z, g0.w, g1.x, g1.y, g1.z, g1.w};
    const float bb[8] = {b0.x, b0.y, b0.z, b0.w, b1.x, b1.y, b1.z, b1.w};

    __half hv[8];
#pragma unroll
    for (int i = 0; i < 8; i++)
        hv[i] = __float2half_rn((v[i] - mean) * rstd * gg[i] + bb[i]);
    *(uint4*)(oh + (size_t)row * D_EMBED + tid * 8) = *(const uint4*)hv;
}

// ---------------- causal softmax in-place on fp16, 1 warp/row ------------------
__global__ void __launch_bounds__(256) softmax_warp(__half* __restrict__ sh)
{
    const int warp = threadIdx.x >> 5, lane = threadIdx.x & 31;
    const int row = blockIdx.x * 8 + warp;       // b*H*T + h*T + t
    const int t = row & (SEQ - 1);
    __half* sr = sh + (size_t)row * SEQ;

    float v[8];
    float mx = -INFINITY;
#pragma unroll
    for (int i = 0; i < 8; i++) {
        const int c = lane + 32 * i;
        v[i] = (c <= t) ? __half2float(sr[c]) : -INFINITY;
        mx = fmaxf(mx, v[i]);
    }
#pragma unroll
    for (int o = 16; o > 0; o >>= 1)
        mx = fmaxf(mx, __shfl_xor_sync(0xFFFFFFFFu, mx, o));

    float sum = 0.f;
#pragma unroll
    for (int i = 0; i < 8; i++) {
        v[i] = expf(v[i] - mx);    // exp(-INF) = 0 for masked lanes
        sum += v[i];
    }
#pragma unroll
    for (int o = 16; o > 0; o >>= 1)
        sum += __shfl_xor_sync(0xFFFFFFFFu, sum, o);
    const float inv = 1.f / sum;

#pragma unroll
    for (int i = 0; i < 8; i++)
        sr[lane + 32 * i] = __float2half_rn(v[i] * inv);
}

// ---------------- final combine: out = x1 + p0 + p1 + bias ---------------------
__global__ void __launch_bounds__(256) combine_out(
    const float* __restrict__ x1, const float* __restrict__ p0,
    const float* __restrict__ p1, const float* __restrict__ b2,
    float* __restrict__ out)
{
    const int i = (blockIdx.x * 256 + threadIdx.x) * 4;
    const int col = i & (D_EMBED - 1);
    const float4 a = *(const float4*)(x1 + i);
    const float4 q = *(const float4*)(p0 + i);
    const float4 r = *(const float4*)(p1 + i);
    const float4 bb = *(const float4*)(b2 + col);
    float4 o;
    o.x = a.x + q.x + r.x + bb.x;
    o.y = a.y + q.y + r.y + bb.y;
    o.z = a.z + q.z + r.z + bb.z;
    o.w = a.w + q.w + r.w + bb.w;
    *(float4*)(out + i) = o;
}

// ---------------- 64x64 transpose: fp32 [rows x lds] -> fp16 [cols x R] --------
__global__ void __launch_bounds__(256) transpose64(
    const float* __restrict__ src, __half* __restrict__ dst,
    int R, int lds)
{
    __shared__ float t[64][65];
    const int c0 = blockIdx.x * 64, r0 = blockIdx.y * 64;
    const int tid = threadIdx.x;
    const int x = tid & 63, yb = tid >> 6;            // 64 x 4
#pragma unroll
    for (int i = 0; i < 64; i += 4)
        t[yb + i][x] = src[(size_t)(r0 + yb + i) * lds + c0 + x];
    __syncthreads();
    const int xw = tid & 31, yw = tid >> 5;           // 32 x 8
#pragma unroll
    for (int i = 0; i < 64; i += 8) {
        const int col = yw + i;
        const __half2 v = __halves2half2(__float2half_rn(t[2*xw][col]),
                                         __float2half_rn(t[2*xw + 1][col]));
        *(__half2*)(dst + (size_t)(c0 + col) * R + r0 + 2*xw) = v;
    }
}

// ---------------- transpose: fp16 [R' x C] -> fp16 [C x R] ---------------------
__global__ void __launch_bounds__(256) transpose_hh(
    const __half* __restrict__ src, __half* __restrict__ dh,
    int R, int lds, int innerCnt, long sO, long sI, long dStride)
{
    __shared__ __half t[32][34];
    const int z = blockIdx.z;
    const int zo = z / innerCnt, zi = z - zo * innerCnt;
    const __half* s = src + (size_t)zo * sO + (size_t)zi * sI;
    __half* hh = dh + (size_t)z * dStride;
    const int c0 = blockIdx.x * 32, r0 = blockIdx.y * 32;
    const int x = threadIdx.x & 31, y = threadIdx.x >> 5;
#pragma unroll
    for (int i = 0; i < 32; i += 8)
        t[y + i][x] = s[(size_t)(r0 + y + i) * lds + c0 + x];
    __syncthreads();
#pragma unroll
    for (int i = 0; i < 32; i += 8)
        hh[(size_t)(c0 + y + i) * R + r0 + x] = t[x][y + i];
}

// ---------------- pack 3 biases into one buffer --------------------------------
__global__ void __launch_bounds__(256) pack3(const float* __restrict__ a,
                                             const float* __restrict__ b,
                                             const float* __restrict__ c,
                                             float* __restrict__ o)
{
    const int i = blockIdx.x * 256 + threadIdx.x;
    o[i] = (i < 2048) ? a[i] : ((i < 4096) ? b[i - 2048] : c[i - 4096]);
}

// ---------------- fp16 mma.sync GEMM: 128x128 tile, 4 warps (64x64), BK=64 -----
// 3-stage cp.async pipeline, 2 CTAs/SM. (round-10 best configuration)
#define EP_BIAS   1
#define EP_GELU   2
#define EP_RES    4
#define EP_HALF   8
#define EP_STOREC 16
#define CZ_SKIP   1     /* skip tiles fully above diagonal (QK^T) */
#define CZ_KCAP   2     /* cap K at bm+128 (AV with causal att)   */

#define BK      64
#define ROWH    72                      /* halves per smem row (pad 64+8)  */
#define ROWB    (ROWH*2)                /* 144 bytes                        */
#define TILE_B  (128 * ROWB)            /* 18432 bytes per tile             */
#define BUF_B   (2 * TILE_B)            /* A,B = 36864                      */
#define SMEM_B  (3 * BUF_B)             /* 3 stages = 110592                */

// load 1/4 of an (A,B) tile pair; part in [0,4)
__device__ __forceinline__ void load_part(const __half* __restrict__ Ag, int lda,
                                          const __half* __restrict__ Bg, int ldb,
                                          int bm, int bn, int k0,
                                          uint32_t sbase, int tid, int part)
{
#pragma unroll
    for (int i = 0; i < 2; i++) {
        const int c = (part * 2 + i) * 128 + tid;   // 0..1023
        const int r = c >> 3, cb = c & 7;
        cp16(sbase + r * ROWB + cb * 16,
             Ag + (size_t)(bm + r) * lda + k0 + cb * 8);
        cp16(sbase + TILE_B + r * ROWB + cb * 16,
             Bg + (size_t)(bn + r) * ldb + k0 + cb * 8);
    }
}

__global__ void __launch_bounds__(128, 2) gemm_hmma(
    const __half* __restrict__ A, const __half* __restrict__ B,
    const float* __restrict__ bias, const float* __restrict__ Rs,
    float* __restrict__ C, __half* __restrict__ Ch,
    int K, int lda, int ldb, int ldc, int innerCnt,
    long aO, long aI, long bO, long bI, long cO, long cI,
    float alpha, int mode, int causal)
{
    extern __shared__ __align__(128) char sm[];

    const int bm = blockIdx.y * 128;
    const int bn = blockIdx.x * 128;
    if ((causal & CZ_SKIP) && bn > bm) return;

    const int tid = threadIdx.x, wid = tid >> 5, lane = tid & 31;
    const int wm = (wid >> 1) * 64;     // 0 or 64
    const int wn = (wid & 1) * 64;      // 0 or 64
    const int lr = lane >> 2;           // 0..7
    const int lc2 = (lane & 3) * 2;     // 0,2,4,6

    // ldmatrix per-lane offsets (halves within a tile)
    const int q = lane >> 3, rw = lane & 7;
    const int aoff = ((q & 1) * 8 + rw) * ROWH + (q >> 1) * 8;
    const int boff = ((q >> 1) * 8 + rw) * ROWH + (q & 1) * 8;

    const int z = blockIdx.z, zo = z / innerCnt, zi = z - zo * innerCnt;
    const __half* Ag = A + (size_t)zo * aO + (size_t)zi * aI;
    const __half* Bg = B + (size_t)zo * bO + (size_t)zi * bI;
    const long coff = (size_t)zo * cO + (size_t)zi * cI;

    const uint32_t sb = smem_u32(sm);
    const int Keff = (causal & CZ_KCAP) ? (bm + 128) : K;
    const int NB = Keff / BK;

    // prologue: stages 0 and 1 (NB >= 2 always for our shapes)
#pragma unroll
    for (int part = 0; part < 4; part++)
        load_part(Ag, lda, Bg, ldb, bm, bn, 0, sb, tid, part);
    CP_COMMIT();
#pragma unroll
    for (int part = 0; part < 4; part++)
        load_part(Ag, lda, Bg, ldb, bm, bn, BK, sb + BUF_B, tid, part);
    CP_COMMIT();

    float acc[4][8][4];
#pragma unroll
    for (int i = 0; i < 4; i++)
#pragma unroll
        for (int j = 0; j < 8; j++)
#pragma unroll
            for (int t = 0; t < 4; t++) acc[i][j][t] = 0.f;

    for (int blk = 0; blk < NB; blk++) {
        if (blk + 1 < NB) cp_wait<1>(); else cp_wait<0>();
        __syncthreads();

        const int stage = blk % 3;
        const uint32_t sA = sb + stage * BUF_B;
        const uint32_t sB = sA + TILE_B;
        const bool next2 = (blk + 2 < NB);
        const int nstage = (blk + 2) % 3;
        const int nk = (blk + 2) * BK;

#pragma unroll
        for (int ks = 0; ks < BK / 16; ks++) {
            const int koff = ks * 16;

            uint32_t aF[4][4];
#pragma unroll
            for (int mt = 0; mt < 4; mt++) {
                const uint32_t ao = (uint32_t)(((wm + mt * 16) * ROWH + koff + aoff) * 2);
                ldsm4(aF[mt][0], aF[mt][1], aF[mt][2], aF[mt][3], sA + ao);
            }
            uint32_t bF[8][2];
#pragma unroll
            for (int p = 0; p < 4; p++) {
                const uint32_t bo = (uint32_t)(((wn + p * 16) * ROWH + koff + boff) * 2);
                ldsm4(bF[2*p][0], bF[2*p][1], bF[2*p+1][0], bF[2*p+1][1], sB + bo);
            }

            if (next2)
                load_part(Ag, lda, Bg, ldb, bm, bn, nk, sb + nstage * BUF_B, tid, ks);

#pragma unroll
            for (int mt = 0; mt < 4; mt++)
#pragma unroll
                for (int nt = 0; nt < 8; nt++)
                    mma16(acc[mt][nt], aF[mt], bF[nt][0], bF[nt][1]);
        }
        if (next2) CP_COMMIT();
    }

    // ---- epilogue ----
#pragma unroll
    for (int mt = 0; mt < 4; mt++) {
#pragma unroll
        for (int half = 0; half < 2; half++) {
            const int rr = bm + wm + mt * 16 + lr + half * 8;
            float* crow = C + coff + (size_t)rr * ldc;
            const float* rrow = Rs + coff + (size_t)rr * ldc;
            __half* hrow = Ch + coff + (size_t)rr * ldc;
#pragma unroll
            for (int nt = 0; nt < 8; nt++) {
                const int col = bn + wn + nt * 8 + lc2;
                float o0 = alpha * acc[mt][nt][half * 2 + 0];
                float o1 = alpha * acc[mt][nt][half * 2 + 1];
                if (mode & EP_BIAS) {
                    const float2 bb = *(const float2*)(bias + col);
                    o0 += bb.x; o1 += bb.y;
                }
                if (mode & EP_GELU) {
                    o0 *= normcdff(o0);
                    o1 *= normcdff(o1);
                }
                if (mode & EP_RES) {
                    const float2 rv = *(const float2*)(rrow + col);
                    o0 += rv.x; o1 += rv.y;
                }
                if (mode & EP_STOREC)
                    *(float2*)(crow + col) = make_float2(o0, o1);
                if (mode & EP_HALF)
                    *(__half2*)(hrow + col) =
                        __halves2half2(__float2half_rn(o0), __float2half_rn(o1));
            }
        }
    }
}

// ---------------- host-side launch helper -------------------------------------
static void gemmH(cudaStream_t st, const __half* A, const __half* B,
                  const float* bias, const float* res,
                  float* C, __half* Ch,
                  int M, int N, int K, int lda, int ldb, int ldc, int mode,
                  float alpha = 1.f, int causal = 0, int batch = 1, int innerCnt = 1,
                  long aO = 0, long aI = 0, long bO = 0, long bI = 0,
                  long cO = 0, long cI = 0)
{
    static int attrDone = 0;
    if (!attrDone) {
        cudaFuncSetAttribute(gemm_hmma, cudaFuncAttributeMaxDynamicSharedMemorySize, SMEM_B);
        attrDone = 1;
    }
    dim3 grid(N / 128, M / 128, batch);
    gemm_hmma<<<grid, 128, SMEM_B, st>>>(A, B, bias, res, C, Ch,
                                         K, lda, ldb, ldc, innerCnt,
                                         aO, aI, bO, bI, cO, cI, alpha, mode, causal);
}

extern "C" void kernel_launch(void* const* d_in, const int* in_sizes, int n_in,
                              void* d_out, int out_size)
{
    const float* x    = (const float*)d_in[0];
    const float* ln1g = (const float*)d_in[1];
    const float* ln1b = (const float*)d_in[2];
    const float* wq   = (const float*)d_in[3];
    const float* bq   = (const float*)d_in[4];
    const float* wk   = (const float*)d_in[5];
    const float* bk   = (const float*)d_in[6];
    const float* wv   = (const float*)d_in[7];
    const float* bv   = (const float*)d_in[8];
    const float* wo   = (const float*)d_in[9];
    const float* bo   = (const float*)d_in[10];
    const float* ln2g = (const float*)d_in[11];
    const float* ln2b = (const float*)d_in[12];
    const float* w1   = (const float*)d_in[13];
    const float* b1   = (const float*)d_in[14];
    const float* w2   = (const float*)d_in[15];
    const float* b2   = (const float*)d_in[16];
    float* out = (float*)d_out;

    void* p;
#define GET(var, symn, T) cudaGetSymbolAddress(&p, symn); T* var = (T*)p
    GET(h,    g_h,    __half);
    GET(qkv,  g_qkv,  __half);
    GET(vt,   g_vt,   __half);
    GET(sh,   g_sh,   __half);
    GET(ao,   g_ao,   __half);
    GET(x1,   g_x1,   float);
    GET(h2,   g_h2,   __half);
    GET(m1,   g_m1,   __half);
    GET(part, g_part, float);
    GET(wqkvt,g_wqkvt,__half);
    GET(wot,  g_wot,  __half);
    GET(w1t,  g_w1t,  __half);
    GET(w2t,  g_w2t,  __half);
    GET(bqkv, g_bqkv, float);
#undef GET

    // side stream + fork/join events (host objects; created once)
    static cudaStream_t s2 = nullptr;
    static cudaEvent_t eFork = nullptr, eQKVw = nullptr, eWlate = nullptr,
                       eQKVdone = nullptr, eVt = nullptr;
    if (!s2) {
        cudaStreamCreateWithFlags(&s2, cudaStreamNonBlocking);
        cudaEventCreateWithFlags(&eFork,    cudaEventDisableTiming);
        cudaEventCreateWithFlags(&eQKVw,    cudaEventDisableTiming);
        cudaEventCreateWithFlags(&eWlate,   cudaEventDisableTiming);
        cudaEventCreateWithFlags(&eQKVdone, cudaEventDisableTiming);
        cudaEventCreateWithFlags(&eVt,      cudaEventDisableTiming);
    }
    const cudaStream_t s0 = 0;

    // ---- fork: prep work on s2 ----
    cudaEventRecord(eFork, s0);
    cudaStreamWaitEvent(s2, eFork, 0);
    {
        dim3 blk(256);
        transpose64<<<dim3(D_EMBED/64, D_EMBED/64), blk, 0, s2>>>(wq, wqkvt,               D_EMBED, D_EMBED);
        transpose64<<<dim3(D_EMBED/64, D_EMBED/64), blk, 0, s2>>>(wk, wqkvt + 2048*2048,   D_EMBED, D_EMBED);
        transpose64<<<dim3(D_EMBED/64, D_EMBED/64), blk, 0, s2>>>(wv, wqkvt + 2*2048*2048, D_EMBED, D_EMBED);
        pack3<<<NQKV/256, 256, 0, s2>>>(bq, bk, bv, bqkv);
        cudaEventRecord(eQKVw, s2);
        // late weights: consumed ~1.5ms later; fully hidden under attention/MLP chain
        transpose64<<<dim3(D_EMBED/64, D_EMBED/64), blk, 0, s2>>>(wo, wot, D_EMBED, D_EMBED);
        transpose64<<<dim3(DFF/64,     D_EMBED/64), blk, 0, s2>>>(w1, w1t, D_EMBED, DFF);
        transpose64<<<dim3(D_EMBED/64, DFF/64),     blk, 0, s2>>>(w2, w2t, DFF,     D_EMBED);
        cudaEventRecord(eWlate, s2);
    }

    // 1. h = LN1(x)   (overlaps qkv weight prep)
    ln_kernel<<<ROWS, 256, 0, s0>>>(x, ln1g, ln1b, h);

    // 2. fused QKV projection (needs wqkvt + bqkv)
    cudaStreamWaitEvent(s0, eQKVw, 0);
    gemmH(s0, h, wqkvt, bqkv, nullptr, nullptr, qkv,
          ROWS, NQKV, D_EMBED, D_EMBED, D_EMBED, NQKV, EP_BIAS | EP_HALF);
    cudaEventRecord(eQKVdone, s0);

    // 3. per-head transpose of V on s2 (hidden under QK + softmax)
    cudaStreamWaitEvent(s2, eQKVdone, 0);
    transpose_hh<<<dim3(HDIM/32, SEQ/32, BH), 256, 0, s2>>>(
        qkv + 4096, vt, SEQ, NQKV, NHEAD,
        (long)SEQ * NQKV, (long)HDIM, (long)SEQ * HDIM);
    cudaEventRecord(eVt, s2);

    // 4. scores = (1/16) Q K^T -> fp16 sh directly (causal tile skip)
    gemmH(s0, qkv, qkv + 2048, nullptr, nullptr, nullptr, sh,
          SEQ, SEQ, HDIM, NQKV, NQKV, SEQ, EP_HALF,
          0.0625f, CZ_SKIP, BH, NHEAD,
          (long)SEQ * NQKV, (long)HDIM,
          (long)SEQ * NQKV, (long)HDIM,
          (long)NHEAD * SEQ * SEQ, (long)SEQ * SEQ);

    // 5. causal softmax (warp-per-row), fp16 in-place
    softmax_warp<<<BH * SEQ / 8, 256, 0, s0>>>(sh);

    // 6. ao = att @ V  (fp16 out; K capped at bm+128 by causality)
    cudaStreamWaitEvent(s0, eVt, 0);
    gemmH(s0, sh, vt, nullptr, nullptr, nullptr, ao,
          SEQ, HDIM, SEQ, SEQ, SEQ, D_EMBED, EP_HALF,
          1.0f, CZ_KCAP, BH, NHEAD,
          (long)NHEAD * SEQ * SEQ, (long)SEQ * SEQ,
          (long)NHEAD * SEQ * HDIM, (long)SEQ * HDIM,
          (long)SEQ * D_EMBED, (long)HDIM);

    // 7. x1 = x + ao @ Wo + bo  (needs wot)
    cudaStreamWaitEvent(s0, eWlate, 0);
    gemmH(s0, ao, wot, bo, x, x1, nullptr,
          ROWS, D_EMBED, D_EMBED, D_EMBED, D_EMBED, D_EMBED,
          EP_BIAS | EP_RES | EP_STOREC);

    // 8. h2 = LN2(x1)
    ln_kernel<<<ROWS, 256, 0, s0>>>(x1, ln2g, ln2b, h2);

    // 9. m1 = gelu(h2 @ W1 + b1) -> fp16
    gemmH(s0, h2, w1t, b1, nullptr, nullptr, m1,
          ROWS, DFF, D_EMBED, D_EMBED, D_EMBED, DFF, EP_BIAS | EP_GELU | EP_HALF);

    // 10. MLP2 split-K=2: partials p0/p1 (raw fp32), 2048 CTAs -> ~7 full waves
    gemmH(s0, m1, w2t, nullptr, nullptr, part, nullptr,
          ROWS, D_EMBED, DFF / 2, DFF, DFF, D_EMBED, EP_STOREC,
          1.0f, 0, /*batch=*/2, /*innerCnt=*/1,
          /*aO=*/DFF / 2, 0, /*bO=*/DFF / 2, 0,
          /*cO=*/(long)ROWS * D_EMBED, 0);

    // 11. out = x1 + p0 + p1 + b2
    combine_out<<<ROWS * D_EMBED / 4 / 256, 256, 0, s0>>>(
        x1, part, part + (size_t)ROWS * D_EMBED, b2, out);
}

// round 17
// speedup vs baseline: 1.0258x; 1.0258x over previous
#include <cuda_runtime.h>
#include <cuda_fp16.h>
#include <math.h>
#include <stdint.h>

#define D_EMBED 2048
#define NHEAD   8
#define HDIM    256
#define BATCH   32
#define SEQ     256
#define ROWS    (BATCH*SEQ)   /* 8192 */
#define DFF     (4*D_EMBED)   /* 8192 */
#define BH      (BATCH*NHEAD) /* 256 */
#define NQKV    (3*D_EMBED)   /* 6144 */

// ---------------- scratch (device globals; no runtime allocation) -------------
__device__ __half g_h  [ROWS*D_EMBED];
__device__ __half g_qkv[(size_t)ROWS*NQKV];
__device__ __half g_vt [ROWS*D_EMBED];
__device__ __half g_sh [BH*SEQ*SEQ];
__device__ __half g_ao [ROWS*D_EMBED];
__device__ float  g_x1 [ROWS*D_EMBED];
__device__ __half g_h2 [ROWS*D_EMBED];
__device__ __half g_m1 [(size_t)ROWS*DFF];
__device__ __half g_wqkvt[(size_t)NQKV*D_EMBED];
__device__ __half g_wot[D_EMBED*D_EMBED];
__device__ __half g_w1t[(size_t)D_EMBED*DFF];
__device__ __half g_w2t[(size_t)D_EMBED*DFF];
__device__ float  g_bqkv[NQKV];

// ---------------- helpers ------------------------------------------------------
__device__ __forceinline__ uint32_t smem_u32(const void* p) {
    uint32_t a;
    asm("{ .reg .u64 t; cvta.to.shared.u64 t, %1; cvt.u32.u64 %0, t; }" : "=r"(a) : "l"(p));
    return a;
}
__device__ __forceinline__ void cp16(uint32_t sdst, const void* gsrc) {
    asm volatile("cp.async.cg.shared.global [%0], [%1], 16;" :: "r"(sdst), "l"(gsrc));
}
#define CP_COMMIT() asm volatile("cp.async.commit_group;" ::: "memory")
template<int N>
__device__ __forceinline__ void cp_wait() {
    asm volatile("cp.async.wait_group %0;" :: "n"(N) : "memory");
}

__device__ __forceinline__ void mma16(float* c, const uint32_t a[4],
                                      uint32_t b0, uint32_t b1) {
    asm volatile(
        "mma.sync.aligned.m16n8k16.row.col.f32.f16.f16.f32 "
        "{%0,%1,%2,%3}, {%4,%5,%6,%7}, {%8,%9}, {%0,%1,%2,%3};"
        : "+f"(c[0]), "+f"(c[1]), "+f"(c[2]), "+f"(c[3])
        : "r"(a[0]), "r"(a[1]), "r"(a[2]), "r"(a[3]), "r"(b0), "r"(b1));
}
__device__ __forceinline__ void ldsm4(uint32_t& r0, uint32_t& r1, uint32_t& r2,
                                      uint32_t& r3, uint32_t addr) {
    asm volatile("ldmatrix.sync.aligned.m8n8.x4.shared.b16 {%0,%1,%2,%3}, [%4];"
                 : "=r"(r0), "=r"(r1), "=r"(r2), "=r"(r3) : "r"(addr));
}

// ---------------- layernorm (fp32 in -> fp16 out), warp-shuffle reductions -----
__global__ void __launch_bounds__(256) ln_kernel(const float* __restrict__ x,
                                                 const float* __restrict__ g,
                                                 const float* __restrict__ b,
                                                 __half* __restrict__ oh)
{
    __shared__ float wsum[8], wsq[8];
    const int row = blockIdx.x;
    const int tid = threadIdx.x;
    const int lane = tid & 31, wid = tid >> 5;
    const float* xr = x + (size_t)row * D_EMBED + tid * 8;

    const float4 a = *(const float4*)(xr);
    const float4 c = *(const float4*)(xr + 4);
    float v[8] = {a.x, a.y, a.z, a.w, c.x, c.y, c.z, c.w};

    float s = 0.f;
#pragma unroll
    for (int i = 0; i < 8; i++) s += v[i];
#pragma unroll
    for (int o = 16; o > 0; o >>= 1) s += __shfl_xor_sync(0xFFFFFFFFu, s, o);
    if (lane == 0) wsum[wid] = s;
    __syncthreads();
    float tot = 0.f;
#pragma unroll
    for (int i = 0; i < 8; i++) tot += wsum[i];
    const float mean = tot * (1.0f / D_EMBED);

    float q = 0.f;
#pragma unroll
    for (int i = 0; i < 8; i++) { const float d = v[i] - mean; q += d * d; }
#pragma unroll
    for (int o = 16; o > 0; o >>= 1) q += __shfl_xor_sync(0xFFFFFFFFu, q, o);
    if (lane == 0) wsq[wid] = q;
    __syncthreads();
    float totq = 0.f;
#pragma unroll
    for (int i = 0; i < 8; i++) totq += wsq[i];
    const float rstd = rsqrtf(totq * (1.0f / D_EMBED) + 1e-5f);

    const float4 g0 = *(const float4*)(g + tid * 8);
    const float4 g1 = *(const float4*)(g + tid * 8 + 4);
    const float4 b0 = *(const float4*)(b + tid * 8);
    const float4 b1 = *(const float4*)(b + tid * 8 + 4);
    const float gg[8] = {g0.x, g0.y, g0.z, g0.w, g1.x, g1.y, g1.z, g1.w};
    const float bb[8] = {b0.x, b0.y, b0.z, b0.w, b1.x, b1.y, b1.z, b1.w};

    __half hv[8];
#pragma unroll
    for (int i = 0; i < 8; i++)
        hv[i] = __float2half_rn((v[i] - mean) * rstd * gg[i] + bb[i]);
    *(uint4*)(oh + (size_t)row * D_EMBED + tid * 8) = *(const uint4*)hv;
}

// ---------------- causal softmax in-place on fp16, 1 warp/row ------------------
__global__ void __launch_bounds__(256) softmax_warp(__half* __restrict__ sh)
{
    const int warp = threadIdx.x >> 5, lane = threadIdx.x & 31;
    const int row = blockIdx.x * 8 + warp;       // (b*H + h)*T + t  (within half)
    const int t = row & (SEQ - 1);
    __half* sr = sh + (size_t)row * SEQ;

    float v[8];
    float mx = -INFINITY;
#pragma unroll
    for (int i = 0; i < 8; i++) {
        const int c = lane + 32 * i;
        v[i] = (c <= t) ? __half2float(sr[c]) : -INFINITY;
        mx = fmaxf(mx, v[i]);
    }
#pragma unroll
    for (int o = 16; o > 0; o >>= 1)
        mx = fmaxf(mx, __shfl_xor_sync(0xFFFFFFFFu, mx, o));

    float sum = 0.f;
#pragma unroll
    for (int i = 0; i < 8; i++) {
        v[i] = __expf(v[i] - mx);   // exp(-INF) = 0 for masked lanes
        sum += v[i];
    }
#pragma unroll
    for (int o = 16; o > 0; o >>= 1)
        sum += __shfl_xor_sync(0xFFFFFFFFu, sum, o);
    const float inv = 1.f / sum;

#pragma unroll
    for (int i = 0; i < 8; i++)
        sr[lane + 32 * i] = __float2half_rn(v[i] * inv);
}

// ---------------- 64x64 transpose: fp32 [rows x lds] -> fp16 [cols x R] --------
__global__ void __launch_bounds__(256) transpose64(
    const float* __restrict__ src, __half* __restrict__ dst,
    int R, int lds)
{
    __shared__ float t[64][65];
    const int c0 = blockIdx.x * 64, r0 = blockIdx.y * 64;
    const int tid = threadIdx.x;
    const int x = tid & 63, yb = tid >> 6;            // 64 x 4
#pragma unroll
    for (int i = 0; i < 64; i += 4)
        t[yb + i][x] = src[(size_t)(r0 + yb + i) * lds + c0 + x];
    __syncthreads();
    const int xw = tid & 31, yw = tid >> 5;           // 32 x 8
#pragma unroll
    for (int i = 0; i < 64; i += 8) {
        const int col = yw + i;
        const __half2 v = __halves2half2(__float2half_rn(t[2*xw][col]),
                                         __float2half_rn(t[2*xw + 1][col]));
        *(__half2*)(dst + (size_t)(c0 + col) * R + r0 + 2*xw) = v;
    }
}

// ---------------- transpose: fp16 [R' x C] -> fp16 [C x R] ---------------------
__global__ void __launch_bounds__(256) transpose_hh(
    const __half* __restrict__ src, __half* __restrict__ dh,
    int R, int lds, int innerCnt, long sO, long sI, long dStride)
{
    __shared__ __half t[32][34];
    const int z = blockIdx.z;
    const int zo = z / innerCnt, zi = z - zo * innerCnt;
    const __half* s = src + (size_t)zo * sO + (size_t)zi * sI;
    __half* hh = dh + (size_t)z * dStride;
    const int c0 = blockIdx.x * 32, r0 = blockIdx.y * 32;
    const int x = threadIdx.x & 31, y = threadIdx.x >> 5;
#pragma unroll
    for (int i = 0; i < 32; i += 8)
        t[y + i][x] = s[(size_t)(r0 + y + i) * lds + c0 + x];
    __syncthreads();
#pragma unroll
    for (int i = 0; i < 32; i += 8)
        hh[(size_t)(c0 + y + i) * R + r0 + x] = t[x][y + i];
}

// ---------------- pack 3 biases into one buffer --------------------------------
__global__ void __launch_bounds__(256) pack3(const float* __restrict__ a,
                                             const float* __restrict__ b,
                                             const float* __restrict__ c,
                                             float* __restrict__ o)
{
    const int i = blockIdx.x * 256 + threadIdx.x;
    o[i] = (i < 2048) ? a[i] : ((i < 4096) ? b[i - 2048] : c[i - 4096]);
}

// ---------------- fp16 mma.sync GEMM: 128x128 tile, 4 warps (64x64), BK=64 -----
// 3-stage cp.async pipeline, 2 CTAs/SM. (round-10 best configuration)
#define EP_BIAS   1
#define EP_GELU   2
#define EP_RES    4
#define EP_HALF   8
#define EP_STOREC 16
#define CZ_SKIP   1     /* skip tiles fully above diagonal (QK^T) */
#define CZ_KCAP   2     /* cap K at bm+128 (AV with causal att)   */

#define BK      64
#define ROWH    72                      /* halves per smem row (pad 64+8)  */
#define ROWB    (ROWH*2)                /* 144 bytes                        */
#define TILE_B  (128 * ROWB)            /* 18432 bytes per tile             */
#define BUF_B   (2 * TILE_B)            /* A,B = 36864                      */
#define SMEM_B  (3 * BUF_B)             /* 3 stages = 110592                */

// load 1/4 of an (A,B) tile pair; part in [0,4)
__device__ __forceinline__ void load_part(const __half* __restrict__ Ag, int lda,
                                          const __half* __restrict__ Bg, int ldb,
                                          int bm, int bn, int k0,
                                          uint32_t sbase, int tid, int part)
{
#pragma unroll
    for (int i = 0; i < 2; i++) {
        const int c = (part * 2 + i) * 128 + tid;   // 0..1023
        const int r = c >> 3, cb = c & 7;
        cp16(sbase + r * ROWB + cb * 16,
             Ag + (size_t)(bm + r) * lda + k0 + cb * 8);
        cp16(sbase + TILE_B + r * ROWB + cb * 16,
             Bg + (size_t)(bn + r) * ldb + k0 + cb * 8);
    }
}

__global__ void __launch_bounds__(128, 2) gemm_hmma(
    const __half* __restrict__ A, const __half* __restrict__ B,
    const float* __restrict__ bias, const float* __restrict__ Rs,
    float* __restrict__ C, __half* __restrict__ Ch,
    int K, int lda, int ldb, int ldc, int innerCnt,
    long aO, long aI, long bO, long bI, long cO, long cI,
    float alpha, int mode, int causal)
{
    extern __shared__ __align__(128) char sm[];

    const int bm = blockIdx.y * 128;
    const int bn = blockIdx.x * 128;
    if ((causal & CZ_SKIP) && bn > bm) return;

    const int tid = threadIdx.x, wid = tid >> 5, lane = tid & 31;
    const int wm = (wid >> 1) * 64;     // 0 or 64
    const int wn = (wid & 1) * 64;      // 0 or 64
    const int lr = lane >> 2;           // 0..7
    const int lc2 = (lane & 3) * 2;     // 0,2,4,6

    // ldmatrix per-lane offsets (halves within a tile)
    const int q = lane >> 3, rw = lane & 7;
    const int aoff = ((q & 1) * 8 + rw) * ROWH + (q >> 1) * 8;
    const int boff = ((q >> 1) * 8 + rw) * ROWH + (q & 1) * 8;

    const int z = blockIdx.z, zo = z / innerCnt, zi = z - zo * innerCnt;
    const __half* Ag = A + (size_t)zo * aO + (size_t)zi * aI;
    const __half* Bg = B + (size_t)zo * bO + (size_t)zi * bI;
    const long coff = (size_t)zo * cO + (size_t)zi * cI;

    const uint32_t sb = smem_u32(sm);
    const int Keff = (causal & CZ_KCAP) ? (bm + 128) : K;
    const int NB = Keff / BK;

    // prologue: stages 0 and 1 (NB >= 2 always for our shapes)
#pragma unroll
    for (int part = 0; part < 4; part++)
        load_part(Ag, lda, Bg, ldb, bm, bn, 0, sb, tid, part);
    CP_COMMIT();
#pragma unroll
    for (int part = 0; part < 4; part++)
        load_part(Ag, lda, Bg, ldb, bm, bn, BK, sb + BUF_B, tid, part);
    CP_COMMIT();

    float acc[4][8][4];
#pragma unroll
    for (int i = 0; i < 4; i++)
#pragma unroll
        for (int j = 0; j < 8; j++)
#pragma unroll
            for (int t = 0; t < 4; t++) acc[i][j][t] = 0.f;

    for (int blk = 0; blk < NB; blk++) {
        if (blk + 1 < NB) cp_wait<1>(); else cp_wait<0>();
        __syncthreads();

        const int stage = blk % 3;
        const uint32_t sA = sb + stage * BUF_B;
        const uint32_t sB = sA + TILE_B;
        const bool next2 = (blk + 2 < NB);
        const int nstage = (blk + 2) % 3;
        const int nk = (blk + 2) * BK;

#pragma unroll
        for (int ks = 0; ks < BK / 16; ks++) {
            const int koff = ks * 16;

            uint32_t aF[4][4];
#pragma unroll
            for (int mt = 0; mt < 4; mt++) {
                const uint32_t ao = (uint32_t)(((wm + mt * 16) * ROWH + koff + aoff) * 2);
                ldsm4(aF[mt][0], aF[mt][1], aF[mt][2], aF[mt][3], sA + ao);
            }
            uint32_t bF[8][2];
#pragma unroll
            for (int p = 0; p < 4; p++) {
                const uint32_t bo = (uint32_t)(((wn + p * 16) * ROWH + koff + boff) * 2);
                ldsm4(bF[2*p][0], bF[2*p][1], bF[2*p+1][0], bF[2*p+1][1], sB + bo);
            }

            if (next2)
                load_part(Ag, lda, Bg, ldb, bm, bn, nk, sb + nstage * BUF_B, tid, ks);

#pragma unroll
            for (int mt = 0; mt < 4; mt++)
#pragma unroll
                for (int nt = 0; nt < 8; nt++)
                    mma16(acc[mt][nt], aF[mt], bF[nt][0], bF[nt][1]);
        }
        if (next2) CP_COMMIT();
    }

    // ---- epilogue ----
#pragma unroll
    for (int mt = 0; mt < 4; mt++) {
#pragma unroll
        for (int half = 0; half < 2; half++) {
            const int rr = bm + wm + mt * 16 + lr + half * 8;
            float* crow = C + coff + (size_t)rr * ldc;
            const float* rrow = Rs + coff + (size_t)rr * ldc;
            __half* hrow = Ch + coff + (size_t)rr * ldc;
#pragma unroll
            for (int nt = 0; nt < 8; nt++) {
                const int col = bn + wn + nt * 8 + lc2;
                float o0 = alpha * acc[mt][nt][half * 2 + 0];
                float o1 = alpha * acc[mt][nt][half * 2 + 1];
                if (mode & EP_BIAS) {
                    const float2 bb = *(const float2*)(bias + col);
                    o0 += bb.x; o1 += bb.y;
                }
                if (mode & EP_GELU) {
                    o0 *= normcdff(o0);
                    o1 *= normcdff(o1);
                }
                if (mode & EP_RES) {
                    const float2 rv = *(const float2*)(rrow + col);
                    o0 += rv.x; o1 += rv.y;
                }
                if (mode & EP_STOREC)
                    *(float2*)(crow + col) = make_float2(o0, o1);
                if (mode & EP_HALF)
                    *(__half2*)(hrow + col) =
                        __halves2half2(__float2half_rn(o0), __float2half_rn(o1));
            }
        }
    }
}

// ---------------- host-side launch helper -------------------------------------
static void gemmH(cudaStream_t st, const __half* A, const __half* B,
                  const float* bias, const float* res,
                  float* C, __half* Ch,
                  int M, int N, int K, int lda, int ldb, int ldc, int mode,
                  float alpha = 1.f, int causal = 0, int batch = 1, int innerCnt = 1,
                  long aO = 0, long aI = 0, long bO = 0, long bI = 0,
                  long cO = 0, long cI = 0)
{
    static int attrDone = 0;
    if (!attrDone) {
        cudaFuncSetAttribute(gemm_hmma, cudaFuncAttributeMaxDynamicSharedMemorySize, SMEM_B);
        attrDone = 1;
    }
    dim3 grid(N / 128, M / 128, batch);
    gemm_hmma<<<grid, 128, SMEM_B, st>>>(A, B, bias, res, C, Ch,
                                         K, lda, ldb, ldc, innerCnt,
                                         aO, aI, bO, bI, cO, cI, alpha, mode, causal);
}

extern "C" void kernel_launch(void* const* d_in, const int* in_sizes, int n_in,
                              void* d_out, int out_size)
{
    const float* x    = (const float*)d_in[0];
    const float* ln1g = (const float*)d_in[1];
    const float* ln1b = (const float*)d_in[2];
    const float* wq   = (const float*)d_in[3];
    const float* bq   = (const float*)d_in[4];
    const float* wk   = (const float*)d_in[5];
    const float* bk   = (const float*)d_in[6];
    const float* wv   = (const float*)d_in[7];
    const float* bv   = (const float*)d_in[8];
    const float* wo   = (const float*)d_in[9];
    const float* bo   = (const float*)d_in[10];
    const float* ln2g = (const float*)d_in[11];
    const float* ln2b = (const float*)d_in[12];
    const float* w1   = (const float*)d_in[13];
    const float* b1   = (const float*)d_in[14];
    const float* w2   = (const float*)d_in[15];
    const float* b2   = (const float*)d_in[16];
    float* out = (float*)d_out;

    void* p;
#define GET(var, symn, T) cudaGetSymbolAddress(&p, symn); T* var = (T*)p
    GET(h,    g_h,    __half);
    GET(qkv,  g_qkv,  __half);
    GET(vt,   g_vt,   __half);
    GET(sh,   g_sh,   __half);
    GET(ao,   g_ao,   __half);
    GET(x1,   g_x1,   float);
    GET(h2,   g_h2,   __half);
    GET(m1,   g_m1,   __half);
    GET(wqkvt,g_wqkvt,__half);
    GET(wot,  g_wot,  __half);
    GET(w1t,  g_w1t,  __half);
    GET(w2t,  g_w2t,  __half);
    GET(bqkv, g_bqkv, float);
#undef GET

    // side stream + fork/join events (host objects; created once)
    static cudaStream_t s2 = nullptr;
    static cudaEvent_t eFork = nullptr, eQKVw = nullptr, eWlate = nullptr,
                       eQKVdone = nullptr, eVt = nullptr, eAtt1 = nullptr;
    if (!s2) {
        cudaStreamCreateWithFlags(&s2, cudaStreamNonBlocking);
        cudaEventCreateWithFlags(&eFork,    cudaEventDisableTiming);
        cudaEventCreateWithFlags(&eQKVw,    cudaEventDisableTiming);
        cudaEventCreateWithFlags(&eWlate,   cudaEventDisableTiming);
        cudaEventCreateWithFlags(&eQKVdone, cudaEventDisableTiming);
        cudaEventCreateWithFlags(&eVt,      cudaEventDisableTiming);
        cudaEventCreateWithFlags(&eAtt1,    cudaEventDisableTiming);
    }
    const cudaStream_t s0 = 0;

    // attention half sizes (split batch 32 -> 16 + 16)
    const int  HB    = BATCH / 2;                      // 16 batches per half
    const long offQ  = (long)HB * SEQ * NQKV;          // qkv offset for half1
    const long offS  = (long)HB * NHEAD * SEQ * SEQ;   // scores offset
    const long offV  = (long)HB * NHEAD * SEQ * HDIM;  // vt offset
    const long offAO = (long)HB * SEQ * D_EMBED;       // ao offset

    // ---- fork: prep work on s2 ----
    cudaEventRecord(eFork, s0);
    cudaStreamWaitEvent(s2, eFork, 0);
    {
        dim3 blk(256);
        transpose64<<<dim3(D_EMBED/64, D_EMBED/64), blk, 0, s2>>>(wq, wqkvt,               D_EMBED, D_EMBED);
        transpose64<<<dim3(D_EMBED/64, D_EMBED/64), blk, 0, s2>>>(wk, wqkvt + 2048*2048,   D_EMBED, D_EMBED);
        transpose64<<<dim3(D_EMBED/64, D_EMBED/64), blk, 0, s2>>>(wv, wqkvt + 2*2048*2048, D_EMBED, D_EMBED);
        pack3<<<NQKV/256, 256, 0, s2>>>(bq, bk, bv, bqkv);
        cudaEventRecord(eQKVw, s2);
        transpose64<<<dim3(D_EMBED/64, D_EMBED/64), blk, 0, s2>>>(wo, wot, D_EMBED, D_EMBED);
        transpose64<<<dim3(DFF/64,     D_EMBED/64), blk, 0, s2>>>(w1, w1t, D_EMBED, DFF);
        transpose64<<<dim3(D_EMBED/64, DFF/64),     blk, 0, s2>>>(w2, w2t, DFF,     D_EMBED);
        cudaEventRecord(eWlate, s2);
    }

    // 1. h = LN1(x)   (overlaps qkv weight prep)
    ln_kernel<<<ROWS, 256, 0, s0>>>(x, ln1g, ln1b, h);

    // 2. fused QKV projection
    cudaStreamWaitEvent(s0, eQKVw, 0);
    gemmH(s0, h, wqkvt, bqkv, nullptr, nullptr, qkv,
          ROWS, NQKV, D_EMBED, D_EMBED, D_EMBED, NQKV, EP_BIAS | EP_HALF);
    cudaEventRecord(eQKVdone, s0);

    // ---- attention, split by batch half across streams ----
    // s2: V transpose (all batches), then half1 QK -> softmax -> AV
    cudaStreamWaitEvent(s2, eQKVdone, 0);
    transpose_hh<<<dim3(HDIM/32, SEQ/32, BH), 256, 0, s2>>>(
        qkv + 4096, vt, SEQ, NQKV, NHEAD,
        (long)SEQ * NQKV, (long)HDIM, (long)SEQ * HDIM);
    cudaEventRecord(eVt, s2);

    gemmH(s2, qkv + offQ, qkv + offQ + 2048, nullptr, nullptr, nullptr, sh + offS,
          SEQ, SEQ, HDIM, NQKV, NQKV, SEQ, EP_HALF,
          0.0625f, CZ_SKIP, HB * NHEAD, NHEAD,
          (long)SEQ * NQKV, (long)HDIM,
          (long)SEQ * NQKV, (long)HDIM,
          (long)NHEAD * SEQ * SEQ, (long)SEQ * SEQ);
    softmax_warp<<<HB * NHEAD * SEQ / 8, 256, 0, s2>>>(sh + offS);
    gemmH(s2, sh + offS, vt + offV, nullptr, nullptr, nullptr, ao + offAO,
          SEQ, HDIM, SEQ, SEQ, SEQ, D_EMBED, EP_HALF,
          1.0f, CZ_KCAP, HB * NHEAD, NHEAD,
          (long)NHEAD * SEQ * SEQ, (long)SEQ * SEQ,
          (long)NHEAD * SEQ * HDIM, (long)SEQ * HDIM,
          (long)SEQ * D_EMBED, (long)HDIM);
    cudaEventRecord(eAtt1, s2);

    // s0: half0 QK -> softmax -> AV
    gemmH(s0, qkv, qkv + 2048, nullptr, nullptr, nullptr, sh,
          SEQ, SEQ, HDIM, NQKV, NQKV, SEQ, EP_HALF,
          0.0625f, CZ_SKIP, HB * NHEAD, NHEAD,
          (long)SEQ * NQKV, (long)HDIM,
          (long)SEQ * NQKV, (long)HDIM,
          (long)NHEAD * SEQ * SEQ, (long)SEQ * SEQ);
    softmax_warp<<<HB * NHEAD * SEQ / 8, 256, 0, s0>>>(sh);
    cudaStreamWaitEvent(s0, eVt, 0);
    gemmH(s0, sh, vt, nullptr, nullptr, nullptr, ao,
          SEQ, HDIM, SEQ, SEQ, SEQ, D_EMBED, EP_HALF,
          1.0f, CZ_KCAP, HB * NHEAD, NHEAD,
          (long)NHEAD * SEQ * SEQ, (long)SEQ * SEQ,
          (long)NHEAD * SEQ * HDIM, (long)SEQ * HDIM,
          (long)SEQ * D_EMBED, (long)HDIM);

    // 7. x1 = x + ao @ Wo + bo  (join half1 + late weights)
    cudaStreamWaitEvent(s0, eAtt1, 0);
    cudaStreamWaitEvent(s0, eWlate, 0);
    gemmH(s0, ao, wot, bo, x, x1, nullptr,
          ROWS, D_EMBED, D_EMBED, D_EMBED, D_EMBED, D_EMBED,
          EP_BIAS | EP_RES | EP_STOREC);

    // 8. h2 = LN2(x1)
    ln_kernel<<<ROWS, 256, 0, s0>>>(x1, ln2g, ln2b, h2);

    // 9. m1 = gelu(h2 @ W1 + b1) -> fp16
    gemmH(s0, h2, w1t, b1, nullptr, nullptr, m1,
          ROWS, DFF, D_EMBED, D_EMBED, D_EMBED, DFF, EP_BIAS | EP_GELU | EP_HALF);

    // 10. out = x1 + m1 @ W2 + b2
    gemmH(s0, m1, w2t, b2, x1, out, nullptr,
          ROWS, D_EMBED, DFF, DFF, DFF, D_EMBED, EP_BIAS | EP_RES | EP_STOREC);
}